// round 12
// baseline (speedup 1.0000x reference)
#include <cuda_runtime.h>
#include <float.h>

// SpatialAttention2D fused, fully register-resident single-read version.
// out[b,c] = sum_hw x[b,c,hw] * softmax_hw(sum_c x[b,c,hw]*w[c] + bias)
// bias softmax-invariant -> never read.
//
// Pass1: grid = 64*32 = 2048 CTAs (b,g), 512 threads, ~90 regs -> 1 CTA/SM.
//   CTA slice: 1024 channels x 32 hw cols (128 KB). Thread (q=tid&7, rg=tid>>3)
//   owns cols [q*4,q*4+4) of rows rg+64k, k=0..15 -> 16 float4 = 64 data regs.
//   Warp-iteration footprint: 4 rows x 128 B dense = 4 fully-used lines/LDG.
//   Phase A: barrier-free stream, v[k] kept in REGISTERS, score partials in-flight.
//   One softmax (warp 0) over the 32 slice scores; 3 CTA barriers total.
//   Phase B: dot(v[k], p) from registers -- NO second memory pass at all.
//   => x is read from DRAM exactly once; L2 read volume ~256 MB (was ~512 MB),
//      LTS cap no longer binding.
// Pass2: log-sum-exp merge of the 32 slice partials per batch.

#define BATCH    64
#define CCH      1024
#define HWN      1024
#define GSPLIT   32
#define SCOLS    32          // hw columns per CTA slice
#define NTHREADS 512
#define PSTRIDE  36          // part row stride (pad 32->36, conflict-free)

__device__ float  g_acc[BATCH * GSPLIT * CCH];   // 8 MB scratch
__device__ float2 g_mz[BATCH * GSPLIT];

struct SMem {
    float w[CCH];              // 4 KB
    float part[64 * PSTRIDE];  // 9.2 KB  score partials part[rg*36 + col]
    float p[SCOLS];            // 128 B
    float outbuf[CCH];         // 4 KB    staging for coalesced scratch store
};

__global__ __launch_bounds__(NTHREADS, 1)
void spatial_attn2d_pass1(const float* __restrict__ x,
                          const float* __restrict__ w)
{
    __shared__ SMem sm;

    const int tid  = threadIdx.x;
    const int lane = tid & 31;
    const int wid  = tid >> 5;
    const int b    = blockIdx.x >> 5;
    const int g    = blockIdx.x & 31;

    const int q  = tid & 7;      // col piece: cols [q*4, q*4+4)
    const int rg = tid >> 3;     // row residue 0..63: rows rg + 64k

    sm.w[tid]       = w[tid];
    sm.w[tid + 512] = w[tid + 512];

    const float* base = x + (size_t)b * CCH * HWN + g * SCOLS + q * 4
                          + (size_t)rg * HWN;

    __syncthreads();   // bar0: weights visible

    // ---------- Phase A: single read, data retained in registers ----------
    float4 v[16];
    float4 ps = make_float4(0.f, 0.f, 0.f, 0.f);
    #pragma unroll
    for (int k = 0; k < 16; k++) {
        v[k] = *(const float4*)(base + (size_t)(64 * k) * HWN);
        float wc = sm.w[rg + 64 * k];
        ps.x = fmaf(v[k].x, wc, ps.x);
        ps.y = fmaf(v[k].y, wc, ps.y);
        ps.z = fmaf(v[k].z, wc, ps.z);
        ps.w = fmaf(v[k].w, wc, ps.w);
    }
    *(float4*)&sm.part[rg * PSTRIDE + q * 4] = ps;
    __syncthreads();   // bar1: partials visible

    // ---------- Softmax over the 32 slice scores (warp 0) ----------
    if (wid == 0) {
        float s = 0.0f;
        #pragma unroll 8
        for (int r = 0; r < 64; r++)
            s += sm.part[r * PSTRIDE + lane];   // conflict-free per iteration
        float m = s;
        #pragma unroll
        for (int o = 16; o; o >>= 1)
            m = fmaxf(m, __shfl_xor_sync(0xffffffffu, m, o));
        float p = __expf(s - m);
        float z = p;
        #pragma unroll
        for (int o = 16; o; o >>= 1)
            z += __shfl_xor_sync(0xffffffffu, z, o);
        sm.p[lane] = p;
        if (lane == 0) g_mz[blockIdx.x] = make_float2(m, z);
    }
    __syncthreads();   // bar2: p visible

    // ---------- Phase B: weighted sums from registers (no memory pass) ------
    const float4 pq = *(const float4*)&sm.p[q * 4];
    #pragma unroll
    for (int k = 0; k < 16; k++) {
        float d = v[k].x * pq.x + v[k].y * pq.y + v[k].z * pq.z + v[k].w * pq.w;
        // reduce over the 8 col-pieces (lane bits 0..2)
        d += __shfl_xor_sync(0xffffffffu, d, 1);
        d += __shfl_xor_sync(0xffffffffu, d, 2);
        d += __shfl_xor_sync(0xffffffffu, d, 4);
        if (q == 0) sm.outbuf[rg + 64 * k] = d;   // lanes 0,8,16,24
    }
    __syncthreads();   // bar3: outbuf complete

    const int slot = blockIdx.x;
    g_acc[(size_t)slot * CCH + tid]       = sm.outbuf[tid];
    g_acc[(size_t)slot * CCH + tid + 512] = sm.outbuf[tid + 512];
}

__global__ __launch_bounds__(128, 8)
void spatial_attn2d_pass2(float* __restrict__ out)
{
    const int b = blockIdx.x >> 3;
    const int c = (blockIdx.x & 7) * 128 + threadIdx.x;

    float M = -FLT_MAX;
    float m[GSPLIT], z[GSPLIT];
    #pragma unroll
    for (int i = 0; i < GSPLIT; i++) {
        float2 mz = g_mz[b * GSPLIT + i];
        m[i] = mz.x; z[i] = mz.y;
        M = fmaxf(M, m[i]);
    }
    float den = 0.0f, num = 0.0f;
    #pragma unroll
    for (int i = 0; i < GSPLIT; i++) {
        float e = __expf(m[i] - M);
        den = fmaf(z[i], e, den);
        num = fmaf(g_acc[(size_t)(b * GSPLIT + i) * CCH + c], e, num);
    }
    out[(size_t)b * CCH + c] = num / den;
}

extern "C" void kernel_launch(void* const* d_in, const int* in_sizes, int n_in,
                              void* d_out, int out_size)
{
    const float* x = (const float*)d_in[0];   // [64,1024,32,32]
    const float* w = (const float*)d_in[1];   // [1024]
    // d_in[2] = attn_b : softmax-invariant, unused
    float* out = (float*)d_out;               // [64,1024]

    spatial_attn2d_pass1<<<BATCH * GSPLIT, NTHREADS>>>(x, w);
    spatial_attn2d_pass2<<<BATCH * 8, 128>>>(out);
}

// round 14
// speedup vs baseline: 1.0247x; 1.0247x over previous
#include <cuda_runtime.h>
#include <float.h>

// SpatialAttention2D fused, cache-resident, 4-CTAs/SM overlap version.
// out[b,c] = sum_hw x[b,c,hw] * softmax_hw(sum_c x[b,c,hw]*w[c] + bias)
// bias softmax-invariant -> never read.
//
// R12 lesson: both cache-resident (R10) and register-resident (R12) pass1 run
// ~4.5 TB/s because at ~1 CTA/SM each CTA's softmax/phase-B/store (~2K cyc) is
// dead DRAM time. Fix = small CTAs (256 thr, 13KB smem, <=64 regs) so 4 CTAs
// co-reside per SM and cover each other's serial phases.
//
// Pass1: grid = 64*32 = 2048 CTAs (b,g), 256 threads, 4 CTAs/SM (~3.5 waves).
//   Slice: 1024 ch x 32 hw cols (128 KB). Thread (q=tid&7, rg=tid>>3) owns
//   cols [q*4,q*4+4) of rows rg+32k, k=0..31. Warp footprint per iter:
//   4 rows x 128 B dense -> 4 fully-used 128B lines per LDG (optimal wavefronts).
//   Phase A: streamed score accumulation (32 LDG/thread, no retention).
//   One softmax (warp 0) over the 32 slice scores. 3 CTA barriers total.
//   Phase B: re-read slice reverse order (L1/L2 hits), dot with p,
//   3-shfl reduce over 8 col-pieces, stage, coalesced store.
// Pass2: float4 loads (4 channels/thread), log-sum-exp merge of 32 partials.

#define BATCH    64
#define CCH      1024
#define HWN      1024
#define GSPLIT   32
#define SCOLS    32
#define NTHREADS 256
#define PSTRIDE  36          // part row stride (pad 32->36)

__device__ float  g_acc[BATCH * GSPLIT * CCH];   // 8 MB scratch
__device__ float2 g_mz[BATCH * GSPLIT];

struct SMem {
    float w[CCH];              // 4 KB
    float part[32 * PSTRIDE];  // 4.6 KB  part[rg*36 + col]
    float p[SCOLS];            // 128 B
    float outbuf[CCH];         // 4 KB
};

__global__ __launch_bounds__(NTHREADS, 4)
void spatial_attn2d_pass1(const float* __restrict__ x,
                          const float* __restrict__ w)
{
    __shared__ SMem sm;

    const int tid  = threadIdx.x;
    const int lane = tid & 31;
    const int wid  = tid >> 5;
    const int b    = blockIdx.x >> 5;
    const int g    = blockIdx.x & 31;

    const int q  = tid & 7;      // col piece: cols [q*4, q*4+4)
    const int rg = tid >> 3;     // row residue 0..31: rows rg + 32k

    sm.w[tid]       = w[tid];
    sm.w[tid + 256] = w[tid + 256];
    sm.w[tid + 512] = w[tid + 512];
    sm.w[tid + 768] = w[tid + 768];

    const float* base = x + (size_t)b * CCH * HWN + g * SCOLS + q * 4
                          + (size_t)rg * HWN;

    __syncthreads();   // bar0: weights visible

    // ---------- Phase A: streamed score partials (no retention) ----------
    float4 ps = make_float4(0.f, 0.f, 0.f, 0.f);
    #pragma unroll 8
    for (int k = 0; k < 32; k++) {
        float4 v = *(const float4*)(base + (size_t)(32 * k) * HWN);
        float wc = sm.w[rg + 32 * k];
        ps.x = fmaf(v.x, wc, ps.x);
        ps.y = fmaf(v.y, wc, ps.y);
        ps.z = fmaf(v.z, wc, ps.z);
        ps.w = fmaf(v.w, wc, ps.w);
    }
    *(float4*)&sm.part[rg * PSTRIDE + q * 4] = ps;
    __syncthreads();   // bar1: partials visible

    // ---------- Softmax over the 32 slice scores (warp 0) ----------
    if (wid == 0) {
        float s = 0.0f;
        #pragma unroll 8
        for (int r = 0; r < 32; r++)
            s += sm.part[r * PSTRIDE + lane];
        float m = s;
        #pragma unroll
        for (int o = 16; o; o >>= 1)
            m = fmaxf(m, __shfl_xor_sync(0xffffffffu, m, o));
        float p = __expf(s - m);
        float z = p;
        #pragma unroll
        for (int o = 16; o; o >>= 1)
            z += __shfl_xor_sync(0xffffffffu, z, o);
        sm.p[lane] = p;
        if (lane == 0) g_mz[blockIdx.x] = make_float2(m, z);
    }
    __syncthreads();   // bar2: p visible

    // ---------- Phase B: re-read reverse order (L1/L2 hits) ----------
    const float4 pq = *(const float4*)&sm.p[q * 4];
    #pragma unroll 8
    for (int kk = 0; kk < 32; kk++) {
        const int k = 31 - kk;                        // newest lines first
        float4 v = *(const float4*)(base + (size_t)(32 * k) * HWN);
        float d = v.x * pq.x + v.y * pq.y + v.z * pq.z + v.w * pq.w;
        d += __shfl_xor_sync(0xffffffffu, d, 1);
        d += __shfl_xor_sync(0xffffffffu, d, 2);
        d += __shfl_xor_sync(0xffffffffu, d, 4);
        if (q == 0) sm.outbuf[rg + 32 * k] = d;       // lanes 0,8,16,24
    }
    __syncthreads();   // bar3: outbuf complete

    const size_t sb = (size_t)blockIdx.x * CCH;
    g_acc[sb + tid]       = sm.outbuf[tid];
    g_acc[sb + tid + 256] = sm.outbuf[tid + 256];
    g_acc[sb + tid + 512] = sm.outbuf[tid + 512];
    g_acc[sb + tid + 768] = sm.outbuf[tid + 768];
}

__global__ __launch_bounds__(128, 8)
void spatial_attn2d_pass2(float* __restrict__ out)
{
    const int b  = blockIdx.x >> 1;
    const int cg = (blockIdx.x & 1) * 128 + threadIdx.x;   // 4-channel group

    float M = -FLT_MAX;
    float m[GSPLIT], z[GSPLIT];
    #pragma unroll
    for (int i = 0; i < GSPLIT; i++) {
        float2 mz = g_mz[b * GSPLIT + i];
        m[i] = mz.x; z[i] = mz.y;
        M = fmaxf(M, m[i]);
    }
    float den = 0.0f;
    float4 num = make_float4(0.f, 0.f, 0.f, 0.f);
    #pragma unroll
    for (int i = 0; i < GSPLIT; i++) {
        float e = __expf(m[i] - M);
        den = fmaf(z[i], e, den);
        float4 a = *(const float4*)(g_acc + (size_t)(b * GSPLIT + i) * CCH + cg * 4);
        num.x = fmaf(a.x, e, num.x);
        num.y = fmaf(a.y, e, num.y);
        num.z = fmaf(a.z, e, num.z);
        num.w = fmaf(a.w, e, num.w);
    }
    const float inv = 1.0f / den;
    float4 r = make_float4(num.x * inv, num.y * inv, num.z * inv, num.w * inv);
    *(float4*)(out + (size_t)b * CCH + cg * 4) = r;
}

extern "C" void kernel_launch(void* const* d_in, const int* in_sizes, int n_in,
                              void* d_out, int out_size)
{
    const float* x = (const float*)d_in[0];   // [64,1024,32,32]
    const float* w = (const float*)d_in[1];   // [1024]
    // d_in[2] = attn_b : softmax-invariant, unused
    float* out = (float*)d_out;               // [64,1024]

    spatial_attn2d_pass1<<<BATCH * GSPLIT, NTHREADS>>>(x, w);
    spatial_attn2d_pass2<<<BATCH * 2, 128>>>(out);
}